// round 4
// baseline (speedup 1.0000x reference)
#include <cuda_runtime.h>
#include <math.h>
#include <stdint.h>

// Problem constants
#define NN      10000
#define EE      320000
#define EALL    (EE + NN)     // edges + self loops = 330000
#define BGRAPH  64
#define NEDGES_OUT 1024

// ---------------- scratch ----------------
__device__ __align__(16) float g_h  [NN * 256];   // post-linear features (pre-bias)
__device__ __align__(16) float g_o1 [NN * 256];
__device__ __align__(16) float g_o2 [NN * 256];
__device__ __align__(16) float g_o3 [NN * 64];
__device__ float g_s  [NN * 4];
__device__ float g_dt [NN * 4];
__device__ int   g_deg[NN + 1];
__device__ int   g_ptr[NN + 1];
__device__ int   g_cur[NN];
__device__ int   g_csr[EALL];

// ---------------- CSR build ----------------
__global__ void zero_deg_kernel() {
    int i = blockIdx.x * blockDim.x + threadIdx.x;
    if (i <= NN) g_deg[i] = 0;
}

__global__ void count_deg_kernel(const int* __restrict__ ei) {
    int e = blockIdx.x * blockDim.x + threadIdx.x;
    if (e >= EALL) return;
    int dst = (e < EE) ? ei[EE + e] : (e - EE);
    atomicAdd(&g_deg[dst], 1);
}

// single-block exclusive scan of g_deg -> g_ptr, also primes g_cur
__global__ void scan_kernel() {
    __shared__ int sh[1024];
    const int t = threadIdx.x;
    const int PER = (NN + 1023) / 1024;
    int start = t * PER;
    int sum = 0;
    for (int i = 0; i < PER; i++) {
        int idx = start + i;
        if (idx < NN) sum += g_deg[idx];
    }
    sh[t] = sum;
    __syncthreads();
    for (int off = 1; off < 1024; off <<= 1) {
        int v = (t >= off) ? sh[t - off] : 0;
        __syncthreads();
        sh[t] += v;
        __syncthreads();
    }
    int run = (t == 0) ? 0 : sh[t - 1];
    for (int i = 0; i < PER; i++) {
        int idx = start + i;
        if (idx < NN) { g_ptr[idx] = run; g_cur[idx] = run; run += g_deg[idx]; }
    }
    if (t == 1023) g_ptr[NN] = sh[1023];
}

__global__ void scatter_kernel(const int* __restrict__ ei) {
    int e = blockIdx.x * blockDim.x + threadIdx.x;
    if (e >= EALL) return;
    int src, dst;
    if (e < EE) { src = ei[e]; dst = ei[EE + e]; }
    else        { src = e - EE; dst = e - EE; }
    int pos = atomicAdd(&g_cur[dst], 1);
    g_csr[pos] = src;
}

// ---------------- SGEMM + fused attention s/d epilogue ----------------
// C = g_h[M, H*64] = A[M,K] @ W[K, H*64]; also g_s[v,h] = h_row·as, g_dt[v,h] = h_row·ad
// Tile: 128 x TN, 256 threads, microtile 8 x (TN/16).
// asel: 0 -> A = Aext, 1 -> g_o1, 2 -> g_o2
template <int TN, int H>
__global__ __launch_bounds__(256)
void sgemm_fused_kernel(const float* __restrict__ Aext, int asel,
                        const float* __restrict__ W,
                        const float* __restrict__ as_, const float* __restrict__ ad_,
                        int M, int K) {
    constexpr int TC = TN / 16;          // cols per thread (8 or 4)
    constexpr int GROUP = 64 / TC;       // threads spanning one head (8 or 16)
    constexpr int NCOL = H * 64;
    const float* __restrict__ A = (asel == 0) ? Aext
                                  : (asel == 1 ? (const float*)g_o1 : (const float*)g_o2);
    __shared__ float sA[16][128];
    __shared__ float sB[16][TN];

    const int t  = threadIdx.x;
    const int tx = t & 15, ty = t >> 4;
    const int brow = blockIdx.y * 128;
    const int bcol = blockIdx.x * TN;

    float acc[8][TC];
#pragma unroll
    for (int i = 0; i < 8; i++)
#pragma unroll
        for (int j = 0; j < TC; j++) acc[i][j] = 0.f;

    const int rowA = t & 127;
    const int kq   = t >> 7;      // 0/1
    const bool arow_ok = (brow + rowA) < M;

    for (int k0 = 0; k0 < K; k0 += 16) {
        // load A tile transposed: sA[k][row]
        float4 v0 = make_float4(0.f,0.f,0.f,0.f), v1 = v0;
        if (arow_ok) {
            const float* ap = A + (size_t)(brow + rowA) * K + k0 + kq * 8;
            v0 = *reinterpret_cast<const float4*>(ap);
            v1 = *reinterpret_cast<const float4*>(ap + 4);
        }
        sA[kq*8+0][rowA] = v0.x; sA[kq*8+1][rowA] = v0.y;
        sA[kq*8+2][rowA] = v0.z; sA[kq*8+3][rowA] = v0.w;
        sA[kq*8+4][rowA] = v1.x; sA[kq*8+5][rowA] = v1.y;
        sA[kq*8+6][rowA] = v1.z; sA[kq*8+7][rowA] = v1.w;
        // load B tile direct: sB[k][col]
        if (TN == 128) {
            int kr = t >> 5, c4 = (t & 31) * 4;
            *reinterpret_cast<float4*>(&sB[kr][c4]) =
                *reinterpret_cast<const float4*>(W + (size_t)(k0 + kr) * NCOL + bcol + c4);
            *reinterpret_cast<float4*>(&sB[kr + 8][c4]) =
                *reinterpret_cast<const float4*>(W + (size_t)(k0 + kr + 8) * NCOL + bcol + c4);
        } else {
            int kr = t >> 4, c4 = (t & 15) * 4;
            *reinterpret_cast<float4*>(&sB[kr][c4]) =
                *reinterpret_cast<const float4*>(W + (size_t)(k0 + kr) * NCOL + bcol + c4);
        }
        __syncthreads();
#pragma unroll
        for (int kk = 0; kk < 16; kk++) {
            float a[8], b[TC];
            float4 A0 = *reinterpret_cast<const float4*>(&sA[kk][ty * 8]);
            float4 A1 = *reinterpret_cast<const float4*>(&sA[kk][ty * 8 + 4]);
            a[0]=A0.x; a[1]=A0.y; a[2]=A0.z; a[3]=A0.w;
            a[4]=A1.x; a[5]=A1.y; a[6]=A1.z; a[7]=A1.w;
            float4 B0 = *reinterpret_cast<const float4*>(&sB[kk][tx * TC]);
            b[0]=B0.x; b[1]=B0.y; b[2]=B0.z; b[3]=B0.w;
            if (TC == 8) {
                float4 B1 = *reinterpret_cast<const float4*>(&sB[kk][tx * TC + 4]);
                b[4]=B1.x; b[5]=B1.y; b[6]=B1.z; b[7]=B1.w;
            }
#pragma unroll
            for (int i = 0; i < 8; i++)
#pragma unroll
                for (int j = 0; j < TC; j++) acc[i][j] += a[i] * b[j];
        }
        __syncthreads();
    }

    // attention vectors for this thread's columns
    const int head = (bcol + tx * TC) >> 6;
    const int cih  = (tx * TC) & 63;   // col-in-head base
    float av[TC], dv[TC];
#pragma unroll
    for (int j = 0; j < TC; j++) {
        av[j] = as_[head * 64 + cih + j];
        dv[j] = ad_[head * 64 + cih + j];
    }

#pragma unroll
    for (int i = 0; i < 8; i++) {
        int r = brow + ty * 8 + i;
        bool ok = r < M;
        // write C
        if (ok) {
            float* cp = g_h + (size_t)r * NCOL + bcol + tx * TC;
#pragma unroll
            for (int j = 0; j < TC; j += 4)
                *reinterpret_cast<float4*>(cp + j) =
                    make_float4(acc[i][j], acc[i][j+1], acc[i][j+2], acc[i][j+3]);
        }
        // s/d partials + reduce across the head's GROUP lanes
        float sv = 0.f, dvv = 0.f;
#pragma unroll
        for (int j = 0; j < TC; j++) { sv += acc[i][j] * av[j]; dvv += acc[i][j] * dv[j]; }
#pragma unroll
        for (int o = GROUP / 2; o > 0; o >>= 1) {
            sv  += __shfl_xor_sync(0xffffffffu, sv, o);
            dvv += __shfl_xor_sync(0xffffffffu, dvv, o);
        }
        if (ok && (tx % GROUP) == 0) {
            g_s [r * H + head] = sv;
            g_dt[r * H + head] = dvv;
        }
    }
}

// ---------------- GAT aggregation: one block per dst node ----------------
template <int H, int C>
__global__ void gat_agg_kernel(const float* __restrict__ bias, int osel) {
    const float* __restrict__ hmat = g_h;
    float* __restrict__ outp = (osel == 1) ? g_o1 : (osel == 2 ? g_o2 : g_o3);
    const int v = blockIdx.x;
    const int t = threadIdx.x;
    const int lane = t & 31, warp = t >> 5;
    const int hd = t / 64;
    const int p0 = g_ptr[v];
    const int deg = g_ptr[v + 1] - p0;
    __shared__ float sh_m[H], sh_ws[H];
    __shared__ int   sh_src[C];
    __shared__ float sh_w[C * H];

    if (warp < H) {
        float dv = g_dt[v * H + warp];
        float mx = -1e30f;
        for (int e = lane; e < deg; e += 32) {
            int sN = g_csr[p0 + e];
            float z = g_s[sN * H + warp] + dv;
            z = z > 0.f ? z : 0.2f * z;
            mx = fmaxf(mx, z);
        }
        for (int o = 16; o > 0; o >>= 1) mx = fmaxf(mx, __shfl_xor_sync(0xffffffffu, mx, o));
        float sum = 0.f;
        for (int e = lane; e < deg; e += 32) {
            int sN = g_csr[p0 + e];
            float z = g_s[sN * H + warp] + dv;
            z = z > 0.f ? z : 0.2f * z;
            sum += __expf(z - mx);
        }
        for (int o = 16; o > 0; o >>= 1) sum += __shfl_xor_sync(0xffffffffu, sum, o);
        if (lane == 0) { sh_m[warp] = mx; sh_ws[warp] = sum; }
    }
    __syncthreads();

    float acc = 0.f;
    for (int base = 0; base < deg; base += C) {
        int cnt = min(C, deg - base);
        if (t < cnt) {
            int sN = g_csr[p0 + base + t];
            sh_src[t] = sN;
#pragma unroll
            for (int hh = 0; hh < H; hh++) {
                float z = g_s[sN * H + hh] + g_dt[v * H + hh];
                z = z > 0.f ? z : 0.2f * z;
                sh_w[t * H + hh] = __expf(z - sh_m[hh]);
            }
        }
        __syncthreads();
        int e = 0;
        for (; e + 3 < cnt; e += 4) {
            float w0 = sh_w[(e + 0) * H + hd], w1 = sh_w[(e + 1) * H + hd];
            float w2 = sh_w[(e + 2) * H + hd], w3 = sh_w[(e + 3) * H + hd];
            float h0 = hmat[(size_t)sh_src[e + 0] * C + t];
            float h1 = hmat[(size_t)sh_src[e + 1] * C + t];
            float h2 = hmat[(size_t)sh_src[e + 2] * C + t];
            float h3 = hmat[(size_t)sh_src[e + 3] * C + t];
            acc += w0 * h0 + w1 * h1 + w2 * h2 + w3 * h3;
        }
        for (; e < cnt; e++) acc += sh_w[e * H + hd] * hmat[(size_t)sh_src[e] * C + t];
        __syncthreads();
    }
    float o = acc / sh_ws[hd] + bias[t];
    outp[(size_t)v * C + t] = fmaxf(o, 0.f);
}

// ---------------- fused pool + actor/critic heads ----------------
// batch is sorted ascending -> per-graph node range via binary search.
__global__ void heads_pool_kernel(const int* __restrict__ batch,
                                  const float* __restrict__ Wa1, const float* __restrict__ ba1,
                                  const float* __restrict__ Wa2, const float* __restrict__ ba2,
                                  const float* __restrict__ Wc1, const float* __restrict__ bc1,
                                  const float* __restrict__ Wc2, const float* __restrict__ bc2,
                                  float* __restrict__ out) {
    const int b = blockIdx.x;
    const int t = threadIdx.x;   // 256
    // lower_bound(batch, b) and lower_bound(batch, b+1)
    int lo = 0, hi = NN;
    while (lo < hi) { int mid = (lo + hi) >> 1; if (batch[mid] < b) lo = mid + 1; else hi = mid; }
    int start = lo;
    lo = start; hi = NN;
    while (lo < hi) { int mid = (lo + hi) >> 1; if (batch[mid] < b + 1) lo = mid + 1; else hi = mid; }
    int end = lo;
    int cnt = end - start;

    __shared__ float red[256];
    __shared__ float p[64], ha[64], hc[64];
    const int c = t & 63, stripe = t >> 6;   // 4 stripes
    float part = 0.f;
    for (int n = start + stripe; n < end; n += 4) part += g_o3[n * 64 + c];
    red[t] = part;
    __syncthreads();
    if (t < 64) {
        float s = red[t] + red[t + 64] + red[t + 128] + red[t + 192];
        float cc = cnt > 0 ? (float)cnt : 1.f;
        p[t] = s / cc;
    }
    __syncthreads();
    if (t < 64) {
        float aa = ba1[t], cv = bc1[t];
        for (int j = 0; j < 64; j++) { aa += p[j] * Wa1[j * 64 + t]; cv += p[j] * Wc1[j * 64 + t]; }
        ha[t] = fmaxf(aa, 0.f);
        hc[t] = fmaxf(cv, 0.f);
    }
    __syncthreads();
    for (int o = t; o < NEDGES_OUT; o += blockDim.x) {
        float acc = ba2[o];
        for (int j = 0; j < 64; j++) acc += ha[j] * Wa2[j * NEDGES_OUT + o];
        out[b * NEDGES_OUT + o] = tanhf(acc);
    }
    if (t == 0) {
        float acc = bc2[0];
        for (int j = 0; j < 64; j++) acc += hc[j] * Wc2[j];
        out[BGRAPH * NEDGES_OUT + b] = acc;
    }
}

// ---------------- launch ----------------
extern "C" void kernel_launch(void* const* d_in, const int* in_sizes, int n_in,
                              void* d_out, int out_size) {
    const float* x     = (const float*)d_in[0];
    const int*   ei    = (const int*)d_in[1];
    const int*   batch = (const int*)d_in[2];
    const float* W1  = (const float*)d_in[3];
    const float* as1 = (const float*)d_in[4];
    const float* ad1 = (const float*)d_in[5];
    const float* b1  = (const float*)d_in[6];
    const float* W2  = (const float*)d_in[7];
    const float* as2 = (const float*)d_in[8];
    const float* ad2 = (const float*)d_in[9];
    const float* b2  = (const float*)d_in[10];
    const float* W3  = (const float*)d_in[11];
    const float* as3 = (const float*)d_in[12];
    const float* ad3 = (const float*)d_in[13];
    const float* b3  = (const float*)d_in[14];
    const float* Wa1 = (const float*)d_in[15];
    const float* ba1 = (const float*)d_in[16];
    const float* Wa2 = (const float*)d_in[17];
    const float* ba2 = (const float*)d_in[18];
    const float* Wc1 = (const float*)d_in[19];
    const float* bc1 = (const float*)d_in[20];
    const float* Wc2 = (const float*)d_in[21];
    const float* bc2 = (const float*)d_in[22];
    float* out = (float*)d_out;

    // CSR build
    zero_deg_kernel<<<(NN + 256) / 256, 256>>>();
    count_deg_kernel<<<(EALL + 255) / 256, 256>>>(ei);
    scan_kernel<<<1, 1024>>>();
    scatter_kernel<<<(EALL + 255) / 256, 256>>>(ei);

    const int MB = (NN + 127) / 128;  // 79

    // Layer 1: K=128, heads=4, Ncol=256
    sgemm_fused_kernel<128, 4><<<dim3(2, MB), 256>>>(x, 0, W1, as1, ad1, NN, 128);
    gat_agg_kernel<4, 256><<<NN, 256>>>(b1, 1);

    // Layer 2: K=256, heads=4, Ncol=256
    sgemm_fused_kernel<128, 4><<<dim3(2, MB), 256>>>(x, 1, W2, as2, ad2, NN, 256);
    gat_agg_kernel<4, 256><<<NN, 256>>>(b2, 2);

    // Layer 3: K=256, heads=1, Ncol=64
    sgemm_fused_kernel<64, 1><<<dim3(1, MB), 256>>>(x, 2, W3, as3, ad3, NN, 256);
    gat_agg_kernel<1, 64><<<NN, 64>>>(b3, 3);

    // fused pool + heads
    heads_pool_kernel<<<BGRAPH, 256>>>(batch, Wa1, ba1, Wa2, ba2, Wc1, bc1, Wc2, bc2, out);
}

// round 5
// speedup vs baseline: 1.0898x; 1.0898x over previous
#include <cuda_runtime.h>
#include <math.h>
#include <stdint.h>

#define NN      10000
#define EE      320000
#define EALL    (EE + NN)
#define BGRAPH  64
#define NEDGES_OUT 1024
#define CAP     256            // smem edge capacity in gat_agg fast path

// ---------------- scratch ----------------
__device__ __align__(16) float g_h  [NN * 256];
__device__ __align__(16) float g_o1 [NN * 256];
__device__ __align__(16) float g_o2 [NN * 256];
__device__ __align__(16) float g_o3 [NN * 64];
__device__ __align__(16) float g_s  [NN * 4];
__device__ __align__(16) float g_dt [NN * 4];
__device__ int   g_deg [NN + 1];
__device__ int   g_ptr [NN + 1];
__device__ int   g_rank[EALL];
__device__ int   g_csr [EALL];

// ---------------- CSR build ----------------
__global__ void zero_deg_kernel() {
    int i = blockIdx.x * blockDim.x + threadIdx.x;
    if (i <= NN) g_deg[i] = 0;
}

// count + record per-edge rank (removes atomic from scatter)
__global__ void count_deg_kernel(const int* __restrict__ ei) {
    int e = blockIdx.x * blockDim.x + threadIdx.x;
    if (e >= EALL) return;
    int dst = (e < EE) ? ei[EE + e] : (e - EE);
    g_rank[e] = atomicAdd(&g_deg[dst], 1);
}

__global__ void scan_kernel() {
    __shared__ int sh[1024];
    const int t = threadIdx.x;
    const int PER = (NN + 1023) / 1024;
    int start = t * PER;
    int sum = 0;
    for (int i = 0; i < PER; i++) {
        int idx = start + i;
        if (idx < NN) sum += g_deg[idx];
    }
    sh[t] = sum;
    __syncthreads();
    for (int off = 1; off < 1024; off <<= 1) {
        int v = (t >= off) ? sh[t - off] : 0;
        __syncthreads();
        sh[t] += v;
        __syncthreads();
    }
    int run = (t == 0) ? 0 : sh[t - 1];
    for (int i = 0; i < PER; i++) {
        int idx = start + i;
        if (idx < NN) { g_ptr[idx] = run; run += g_deg[idx]; }
    }
    if (t == 1023) g_ptr[NN] = sh[1023];
}

__global__ void scatter_kernel(const int* __restrict__ ei) {
    int e = blockIdx.x * blockDim.x + threadIdx.x;
    if (e >= EALL) return;
    int src, dst;
    if (e < EE) { src = ei[e]; dst = ei[EE + e]; }
    else        { src = e - EE; dst = e - EE; }
    g_csr[g_ptr[dst] + g_rank[e]] = src;
}

// ---------------- SGEMM + fused attention s/d epilogue ----------------
template <int TN, int H>
__global__ __launch_bounds__(256)
void sgemm_fused_kernel(const float* __restrict__ Aext, int asel,
                        const float* __restrict__ W,
                        const float* __restrict__ as_, const float* __restrict__ ad_,
                        int M, int K) {
    constexpr int TC = TN / 16;
    constexpr int GROUP = 64 / TC;
    constexpr int NCOL = H * 64;
    const float* __restrict__ A = (asel == 0) ? Aext
                                  : (asel == 1 ? (const float*)g_o1 : (const float*)g_o2);
    __shared__ float sA[16][128];
    __shared__ float sB[16][TN];

    const int t  = threadIdx.x;
    const int tx = t & 15, ty = t >> 4;
    const int brow = blockIdx.y * 128;
    const int bcol = blockIdx.x * TN;

    float acc[8][TC];
#pragma unroll
    for (int i = 0; i < 8; i++)
#pragma unroll
        for (int j = 0; j < TC; j++) acc[i][j] = 0.f;

    const int rowA = t & 127;
    const int kq   = t >> 7;
    const bool arow_ok = (brow + rowA) < M;

    for (int k0 = 0; k0 < K; k0 += 16) {
        float4 v0 = make_float4(0.f,0.f,0.f,0.f), v1 = v0;
        if (arow_ok) {
            const float* ap = A + (size_t)(brow + rowA) * K + k0 + kq * 8;
            v0 = *reinterpret_cast<const float4*>(ap);
            v1 = *reinterpret_cast<const float4*>(ap + 4);
        }
        sA[kq*8+0][rowA] = v0.x; sA[kq*8+1][rowA] = v0.y;
        sA[kq*8+2][rowA] = v0.z; sA[kq*8+3][rowA] = v0.w;
        sA[kq*8+4][rowA] = v1.x; sA[kq*8+5][rowA] = v1.y;
        sA[kq*8+6][rowA] = v1.z; sA[kq*8+7][rowA] = v1.w;
        if (TN == 128) {
            int kr = t >> 5, c4 = (t & 31) * 4;
            *reinterpret_cast<float4*>(&sB[kr][c4]) =
                *reinterpret_cast<const float4*>(W + (size_t)(k0 + kr) * NCOL + bcol + c4);
            *reinterpret_cast<float4*>(&sB[kr + 8][c4]) =
                *reinterpret_cast<const float4*>(W + (size_t)(k0 + kr + 8) * NCOL + bcol + c4);
        } else {
            int kr = t >> 4, c4 = (t & 15) * 4;
            *reinterpret_cast<float4*>(&sB[kr][c4]) =
                *reinterpret_cast<const float4*>(W + (size_t)(k0 + kr) * NCOL + bcol + c4);
        }
        __syncthreads();
#pragma unroll
        for (int kk = 0; kk < 16; kk++) {
            float a[8], b[TC];
            float4 A0 = *reinterpret_cast<const float4*>(&sA[kk][ty * 8]);
            float4 A1 = *reinterpret_cast<const float4*>(&sA[kk][ty * 8 + 4]);
            a[0]=A0.x; a[1]=A0.y; a[2]=A0.z; a[3]=A0.w;
            a[4]=A1.x; a[5]=A1.y; a[6]=A1.z; a[7]=A1.w;
            float4 B0 = *reinterpret_cast<const float4*>(&sB[kk][tx * TC]);
            b[0]=B0.x; b[1]=B0.y; b[2]=B0.z; b[3]=B0.w;
            if (TC == 8) {
                float4 B1 = *reinterpret_cast<const float4*>(&sB[kk][tx * TC + 4]);
                b[4]=B1.x; b[5]=B1.y; b[6]=B1.z; b[7]=B1.w;
            }
#pragma unroll
            for (int i = 0; i < 8; i++)
#pragma unroll
                for (int j = 0; j < TC; j++) acc[i][j] += a[i] * b[j];
        }
        __syncthreads();
    }

    const int head = (bcol + tx * TC) >> 6;
    const int cih  = (tx * TC) & 63;
    float av[TC], dv[TC];
#pragma unroll
    for (int j = 0; j < TC; j++) {
        av[j] = as_[head * 64 + cih + j];
        dv[j] = ad_[head * 64 + cih + j];
    }

#pragma unroll
    for (int i = 0; i < 8; i++) {
        int r = brow + ty * 8 + i;
        bool ok = r < M;
        if (ok) {
            float* cp = g_h + (size_t)r * NCOL + bcol + tx * TC;
#pragma unroll
            for (int j = 0; j < TC; j += 4)
                *reinterpret_cast<float4*>(cp + j) =
                    make_float4(acc[i][j], acc[i][j+1], acc[i][j+2], acc[i][j+3]);
        }
        float sv = 0.f, dvv = 0.f;
#pragma unroll
        for (int j = 0; j < TC; j++) { sv += acc[i][j] * av[j]; dvv += acc[i][j] * dv[j]; }
#pragma unroll
        for (int o = GROUP / 2; o > 0; o >>= 1) {
            sv  += __shfl_xor_sync(0xffffffffu, sv, o);
            dvv += __shfl_xor_sync(0xffffffffu, dvv, o);
        }
        if (ok && (tx % GROUP) == 0) {
            // padded stride-4 layout for both H=4 and H=1 (float4-aligned rows)
            g_s [r * 4 + head] = sv;
            g_dt[r * 4 + head] = dvv;
        }
    }
}

__device__ __forceinline__ float leaky02(float z) { return z > 0.f ? z : 0.2f * z; }

// ---------------- GAT aggregation: one block per dst node ----------------
// C = channels = blockDim.x. Fast path deg<=CAP: g_s loaded ONCE per edge (float4),
// softmax entirely in smem. Fallback chunked path for deg>CAP.
template <int H, int C>
__global__ void gat_agg_kernel(const float* __restrict__ bias, int osel) {
    const float* __restrict__ hmat = g_h;
    float* __restrict__ outp = (osel == 1) ? g_o1 : (osel == 2 ? g_o2 : g_o3);
    const int v = blockIdx.x;
    const int t = threadIdx.x;
    const int lane = t & 31, warp = t >> 5;
    const int hd = t >> 6;                 // head of this channel
    const int p0 = g_ptr[v];
    const int deg = g_ptr[v + 1] - p0;

    __shared__ float sh_ws[H];
    __shared__ float sh_m[H];
    __shared__ int   sh_src[CAP];
    __shared__ float sh_w[CAP * H];

    // dst attention terms (stride-4 padded layout)
    float dt[H];
    if (H == 4) {
        float4 d4 = *reinterpret_cast<const float4*>(&g_dt[v * 4]);
        dt[0] = d4.x; dt[1] = d4.y; dt[2] = d4.z; dt[3] = d4.w;
    } else {
        dt[0] = g_dt[v * 4];
    }

    if (deg <= CAP) {
        // ---- fast path ----
        for (int e = t; e < deg; e += C) {
            int sN = g_csr[p0 + e];
            sh_src[e] = sN;
            if (H == 4) {
                float4 s4 = *reinterpret_cast<const float4*>(&g_s[sN * 4]);
                sh_w[e * 4 + 0] = leaky02(s4.x + dt[0]);
                sh_w[e * 4 + 1] = leaky02(s4.y + dt[1]);
                sh_w[e * 4 + 2] = leaky02(s4.z + dt[2]);
                sh_w[e * 4 + 3] = leaky02(s4.w + dt[3]);
            } else {
                sh_w[e] = leaky02(g_s[sN * 4] + dt[0]);
            }
        }
        __syncthreads();
        if (warp < H) {
            float mx = -1e30f;
            for (int e = lane; e < deg; e += 32) mx = fmaxf(mx, sh_w[e * H + warp]);
#pragma unroll
            for (int o = 16; o > 0; o >>= 1) mx = fmaxf(mx, __shfl_xor_sync(0xffffffffu, mx, o));
            float sum = 0.f;
            for (int e = lane; e < deg; e += 32) {
                float w_ = __expf(sh_w[e * H + warp] - mx);
                sh_w[e * H + warp] = w_;
                sum += w_;
            }
#pragma unroll
            for (int o = 16; o > 0; o >>= 1) sum += __shfl_xor_sync(0xffffffffu, sum, o);
            if (lane == 0) sh_ws[warp] = sum;
        }
        __syncthreads();

        float acc = 0.f;
        int e = 0;
        for (; e + 3 < deg; e += 4) {
            float w0 = sh_w[(e + 0) * H + hd], w1 = sh_w[(e + 1) * H + hd];
            float w2 = sh_w[(e + 2) * H + hd], w3 = sh_w[(e + 3) * H + hd];
            float h0 = hmat[(size_t)sh_src[e + 0] * (H * 64) + t];
            float h1 = hmat[(size_t)sh_src[e + 1] * (H * 64) + t];
            float h2 = hmat[(size_t)sh_src[e + 2] * (H * 64) + t];
            float h3 = hmat[(size_t)sh_src[e + 3] * (H * 64) + t];
            acc += w0 * h0 + w1 * h1 + w2 * h2 + w3 * h3;
        }
        for (; e < deg; e++) acc += sh_w[e * H + hd] * hmat[(size_t)sh_src[e] * (H * 64) + t];
        float o = acc / sh_ws[hd] + bias[t];
        outp[(size_t)v * (H * 64) + t] = fmaxf(o, 0.f);
        return;
    }

    // ---- fallback: deg > CAP (rare) ----
    if (warp < H) {
        float mx = -1e30f;
        for (int e = lane; e < deg; e += 32) {
            int sN = g_csr[p0 + e];
            mx = fmaxf(mx, leaky02(g_s[sN * 4 + warp] + dt[warp]));
        }
#pragma unroll
        for (int o = 16; o > 0; o >>= 1) mx = fmaxf(mx, __shfl_xor_sync(0xffffffffu, mx, o));
        float sum = 0.f;
        for (int e = lane; e < deg; e += 32) {
            int sN = g_csr[p0 + e];
            sum += __expf(leaky02(g_s[sN * 4 + warp] + dt[warp]) - mx);
        }
#pragma unroll
        for (int o = 16; o > 0; o >>= 1) sum += __shfl_xor_sync(0xffffffffu, sum, o);
        if (lane == 0) { sh_m[warp] = mx; sh_ws[warp] = sum; }
    }
    __syncthreads();

    float acc = 0.f;
    for (int base = 0; base < deg; base += CAP) {
        int cnt = min(CAP, deg - base);
        for (int e = t; e < cnt; e += C) {
            int sN = g_csr[p0 + base + e];
            sh_src[e] = sN;
#pragma unroll
            for (int hh = 0; hh < H; hh++)
                sh_w[e * H + hh] = __expf(leaky02(g_s[sN * 4 + hh] + dt[hh]) - sh_m[hh]);
        }
        __syncthreads();
        for (int e = 0; e < cnt; e++)
            acc += sh_w[e * H + hd] * hmat[(size_t)sh_src[e] * (H * 64) + t];
        __syncthreads();
    }
    float o = acc / sh_ws[hd] + bias[t];
    outp[(size_t)v * (H * 64) + t] = fmaxf(o, 0.f);
}

// ---------------- fused pool + actor/critic heads ----------------
__global__ void heads_pool_kernel(const int* __restrict__ batch,
                                  const float* __restrict__ Wa1, const float* __restrict__ ba1,
                                  const float* __restrict__ Wa2, const float* __restrict__ ba2,
                                  const float* __restrict__ Wc1, const float* __restrict__ bc1,
                                  const float* __restrict__ Wc2, const float* __restrict__ bc2,
                                  float* __restrict__ out) {
    const int b = blockIdx.x;
    const int t = threadIdx.x;
    int lo = 0, hi = NN;
    while (lo < hi) { int mid = (lo + hi) >> 1; if (batch[mid] < b) lo = mid + 1; else hi = mid; }
    int start = lo;
    lo = start; hi = NN;
    while (lo < hi) { int mid = (lo + hi) >> 1; if (batch[mid] < b + 1) lo = mid + 1; else hi = mid; }
    int end = lo;
    int cnt = end - start;

    __shared__ float red[256];
    __shared__ float p[64], ha[64], hc[64];
    const int c = t & 63, stripe = t >> 6;
    float part = 0.f;
    for (int n = start + stripe; n < end; n += 4) part += g_o3[n * 64 + c];
    red[t] = part;
    __syncthreads();
    if (t < 64) {
        float s = red[t] + red[t + 64] + red[t + 128] + red[t + 192];
        float cc = cnt > 0 ? (float)cnt : 1.f;
        p[t] = s / cc;
    }
    __syncthreads();
    if (t < 64) {
        float aa = ba1[t], cv = bc1[t];
        for (int j = 0; j < 64; j++) { aa += p[j] * Wa1[j * 64 + t]; cv += p[j] * Wc1[j * 64 + t]; }
        ha[t] = fmaxf(aa, 0.f);
        hc[t] = fmaxf(cv, 0.f);
    }
    __syncthreads();
    for (int o = t; o < NEDGES_OUT; o += blockDim.x) {
        float acc = ba2[o];
        for (int j = 0; j < 64; j++) acc += ha[j] * Wa2[j * NEDGES_OUT + o];
        out[b * NEDGES_OUT + o] = tanhf(acc);
    }
    if (t == 0) {
        float acc = bc2[0];
        for (int j = 0; j < 64; j++) acc += hc[j] * Wc2[j];
        out[BGRAPH * NEDGES_OUT + b] = acc;
    }
}

// ---------------- launch ----------------
extern "C" void kernel_launch(void* const* d_in, const int* in_sizes, int n_in,
                              void* d_out, int out_size) {
    const float* x     = (const float*)d_in[0];
    const int*   ei    = (const int*)d_in[1];
    const int*   batch = (const int*)d_in[2];
    const float* W1  = (const float*)d_in[3];
    const float* as1 = (const float*)d_in[4];
    const float* ad1 = (const float*)d_in[5];
    const float* b1  = (const float*)d_in[6];
    const float* W2  = (const float*)d_in[7];
    const float* as2 = (const float*)d_in[8];
    const float* ad2 = (const float*)d_in[9];
    const float* b2  = (const float*)d_in[10];
    const float* W3  = (const float*)d_in[11];
    const float* as3 = (const float*)d_in[12];
    const float* ad3 = (const float*)d_in[13];
    const float* b3  = (const float*)d_in[14];
    const float* Wa1 = (const float*)d_in[15];
    const float* ba1 = (const float*)d_in[16];
    const float* Wa2 = (const float*)d_in[17];
    const float* ba2 = (const float*)d_in[18];
    const float* Wc1 = (const float*)d_in[19];
    const float* bc1 = (const float*)d_in[20];
    const float* Wc2 = (const float*)d_in[21];
    const float* bc2 = (const float*)d_in[22];
    float* out = (float*)d_out;

    zero_deg_kernel<<<(NN + 256) / 256, 256>>>();
    count_deg_kernel<<<(EALL + 255) / 256, 256>>>(ei);
    scan_kernel<<<1, 1024>>>();
    scatter_kernel<<<(EALL + 255) / 256, 256>>>(ei);

    const int MB = (NN + 127) / 128;

    sgemm_fused_kernel<128, 4><<<dim3(2, MB), 256>>>(x, 0, W1, as1, ad1, NN, 128);
    gat_agg_kernel<4, 256><<<NN, 256>>>(b1, 1);

    sgemm_fused_kernel<128, 4><<<dim3(2, MB), 256>>>(x, 1, W2, as2, ad2, NN, 256);
    gat_agg_kernel<4, 256><<<NN, 256>>>(b2, 2);

    sgemm_fused_kernel<64, 1><<<dim3(1, MB), 256>>>(x, 2, W3, as3, ad3, NN, 256);
    gat_agg_kernel<1, 64><<<NN, 64>>>(b3, 3);

    heads_pool_kernel<<<BGRAPH, 256>>>(batch, Wa1, ba1, Wa2, ba2, Wc1, bc1, Wc2, bc2, out);
}

// round 6
// speedup vs baseline: 1.2814x; 1.1759x over previous
#include <cuda_runtime.h>
#include <math.h>
#include <stdint.h>

#define NN      10000
#define EE      320000
#define EALL    (EE + NN)
#define BGRAPH  64
#define NEDGES_OUT 1024
#define CAP     256

// ---------------- scratch ----------------
__device__ __align__(16) float g_h  [NN * 256];
__device__ __align__(16) float g_o1 [NN * 256];
__device__ __align__(16) float g_o2 [NN * 256];
__device__ __align__(16) float g_o3 [NN * 64];
__device__ __align__(16) float g_s  [NN * 4];
__device__ __align__(16) float g_dt [NN * 4];
__device__ int   g_deg [NN + 1];
__device__ int   g_ptr [NN + 1];
__device__ int   g_rank[EALL];
__device__ int   g_csr [EALL];

// ---------------- f32x2 helpers ----------------
__device__ __forceinline__ uint64_t pk2(float lo, float hi) {
    uint64_t r; asm("mov.b64 %0,{%1,%2};" : "=l"(r) : "f"(lo), "f"(hi)); return r;
}
__device__ __forceinline__ void fma2(uint64_t& d, uint64_t a, uint64_t b) {
    asm("fma.rn.f32x2 %0,%1,%2,%0;" : "+l"(d) : "l"(a), "l"(b));
}
__device__ __forceinline__ float2 upk2(uint64_t v) {
    float2 r; asm("mov.b64 {%0,%1},%2;" : "=f"(r.x), "=f"(r.y) : "l"(v)); return r;
}
__device__ __forceinline__ float leaky02(float z) { return z > 0.f ? z : 0.2f * z; }

// ---------------- CSR build ----------------
__global__ void zero_deg_kernel() {
    int i = blockIdx.x * blockDim.x + threadIdx.x;
    if (i <= NN) g_deg[i] = 0;
}

__global__ void count_deg_kernel(const int* __restrict__ ei) {
    int e = blockIdx.x * blockDim.x + threadIdx.x;
    if (e >= EALL) return;
    int dst = (e < EE) ? ei[EE + e] : (e - EE);
    g_rank[e] = atomicAdd(&g_deg[dst], 1);
}

__global__ void scan_kernel() {
    __shared__ int sh[1024];
    const int t = threadIdx.x;
    const int PER = (NN + 1023) / 1024;
    int start = t * PER;
    int sum = 0;
    for (int i = 0; i < PER; i++) {
        int idx = start + i;
        if (idx < NN) sum += g_deg[idx];
    }
    sh[t] = sum;
    __syncthreads();
    for (int off = 1; off < 1024; off <<= 1) {
        int v = (t >= off) ? sh[t - off] : 0;
        __syncthreads();
        sh[t] += v;
        __syncthreads();
    }
    int run = (t == 0) ? 0 : sh[t - 1];
    for (int i = 0; i < PER; i++) {
        int idx = start + i;
        if (idx < NN) { g_ptr[idx] = run; run += g_deg[idx]; }
    }
    if (t == 1023) g_ptr[NN] = sh[1023];
}

__global__ void scatter_kernel(const int* __restrict__ ei) {
    int e = blockIdx.x * blockDim.x + threadIdx.x;
    if (e >= EALL) return;
    int src, dst;
    if (e < EE) { src = ei[e]; dst = ei[EE + e]; }
    else        { src = e - EE; dst = e - EE; }
    g_csr[g_ptr[dst] + g_rank[e]] = src;
}

// ---------------- SGEMM (f32x2) + fused attention s/d epilogue ----------------
template <int TN, int H>
__global__ __launch_bounds__(256)
void sgemm_fused_kernel(const float* __restrict__ Aext, int asel,
                        const float* __restrict__ W,
                        const float* __restrict__ as_, const float* __restrict__ ad_,
                        int M, int K) {
    constexpr int TC = TN / 16;          // 8 or 4 cols/thread
    constexpr int TP = TC / 2;           // packed pairs
    constexpr int GROUP = 64 / TC;
    constexpr int NCOL = H * 64;
    const float* __restrict__ A = (asel == 0) ? Aext
                                  : (asel == 1 ? (const float*)g_o1 : (const float*)g_o2);
    __shared__ float sA[16][128];
    __shared__ float sB[16][TN];

    const int t  = threadIdx.x;
    const int tx = t & 15, ty = t >> 4;
    const int brow = blockIdx.y * 128;
    const int bcol = blockIdx.x * TN;

    uint64_t accp[8][TP];
#pragma unroll
    for (int i = 0; i < 8; i++)
#pragma unroll
        for (int j = 0; j < TP; j++) accp[i][j] = 0ull;

    const int rowA = t & 127;
    const int kq   = t >> 7;
    const bool arow_ok = (brow + rowA) < M;

    for (int k0 = 0; k0 < K; k0 += 16) {
        float4 v0 = make_float4(0.f,0.f,0.f,0.f), v1 = v0;
        if (arow_ok) {
            const float* ap = A + (size_t)(brow + rowA) * K + k0 + kq * 8;
            v0 = *reinterpret_cast<const float4*>(ap);
            v1 = *reinterpret_cast<const float4*>(ap + 4);
        }
        sA[kq*8+0][rowA] = v0.x; sA[kq*8+1][rowA] = v0.y;
        sA[kq*8+2][rowA] = v0.z; sA[kq*8+3][rowA] = v0.w;
        sA[kq*8+4][rowA] = v1.x; sA[kq*8+5][rowA] = v1.y;
        sA[kq*8+6][rowA] = v1.z; sA[kq*8+7][rowA] = v1.w;
        if (TN == 128) {
            int kr = t >> 5, c4 = (t & 31) * 4;
            *reinterpret_cast<float4*>(&sB[kr][c4]) =
                *reinterpret_cast<const float4*>(W + (size_t)(k0 + kr) * NCOL + bcol + c4);
            *reinterpret_cast<float4*>(&sB[kr + 8][c4]) =
                *reinterpret_cast<const float4*>(W + (size_t)(k0 + kr + 8) * NCOL + bcol + c4);
        } else {
            int kr = t >> 4, c4 = (t & 15) * 4;
            *reinterpret_cast<float4*>(&sB[kr][c4]) =
                *reinterpret_cast<const float4*>(W + (size_t)(k0 + kr) * NCOL + bcol + c4);
        }
        __syncthreads();
#pragma unroll
        for (int kk = 0; kk < 16; kk++) {
            float4 A0 = *reinterpret_cast<const float4*>(&sA[kk][ty * 8]);
            float4 A1 = *reinterpret_cast<const float4*>(&sA[kk][ty * 8 + 4]);
            uint64_t ap[8];
            ap[0]=pk2(A0.x,A0.x); ap[1]=pk2(A0.y,A0.y); ap[2]=pk2(A0.z,A0.z); ap[3]=pk2(A0.w,A0.w);
            ap[4]=pk2(A1.x,A1.x); ap[5]=pk2(A1.y,A1.y); ap[6]=pk2(A1.z,A1.z); ap[7]=pk2(A1.w,A1.w);
            uint64_t bp[TP];
            float4 B0 = *reinterpret_cast<const float4*>(&sB[kk][tx * TC]);
            bp[0]=pk2(B0.x,B0.y); bp[1]=pk2(B0.z,B0.w);
            if (TC == 8) {
                float4 B1 = *reinterpret_cast<const float4*>(&sB[kk][tx * TC + 4]);
                bp[2]=pk2(B1.x,B1.y); bp[3]=pk2(B1.z,B1.w);
            }
#pragma unroll
            for (int i = 0; i < 8; i++)
#pragma unroll
                for (int j = 0; j < TP; j++) fma2(accp[i][j], ap[i], bp[j]);
        }
        __syncthreads();
    }

    // unpack accumulators
    float acc[8][TC];
#pragma unroll
    for (int i = 0; i < 8; i++)
#pragma unroll
        for (int j = 0; j < TP; j++) {
            float2 u = upk2(accp[i][j]);
            acc[i][2*j] = u.x; acc[i][2*j+1] = u.y;
        }

    const int head = (bcol + tx * TC) >> 6;
    const int cih  = (tx * TC) & 63;
    float av[TC], dv[TC];
#pragma unroll
    for (int j = 0; j < TC; j++) {
        av[j] = as_[head * 64 + cih + j];
        dv[j] = ad_[head * 64 + cih + j];
    }

#pragma unroll
    for (int i = 0; i < 8; i++) {
        int r = brow + ty * 8 + i;
        bool ok = r < M;
        if (ok) {
            float* cp = g_h + (size_t)r * NCOL + bcol + tx * TC;
#pragma unroll
            for (int j = 0; j < TC; j += 4)
                *reinterpret_cast<float4*>(cp + j) =
                    make_float4(acc[i][j], acc[i][j+1], acc[i][j+2], acc[i][j+3]);
        }
        float sv = 0.f, dvv = 0.f;
#pragma unroll
        for (int j = 0; j < TC; j++) { sv += acc[i][j] * av[j]; dvv += acc[i][j] * dv[j]; }
#pragma unroll
        for (int o = GROUP / 2; o > 0; o >>= 1) {
            sv  += __shfl_xor_sync(0xffffffffu, sv, o);
            dvv += __shfl_xor_sync(0xffffffffu, dvv, o);
        }
        if (ok && (tx % GROUP) == 0) {
            g_s [r * 4 + head] = sv;
            g_dt[r * 4 + head] = dvv;
        }
    }
}

// ---------------- GAT aggregation H=4, vectorized: 64 threads, float4/thread ----------------
__global__ void gat_agg4_kernel(const float* __restrict__ bias, int osel) {
    float* __restrict__ outp = (osel == 1) ? g_o1 : g_o2;
    const int v = blockIdx.x;
    const int t = threadIdx.x;          // 64
    const int lane = t & 31, warp = t >> 5;
    const int hd = t >> 4;              // head of channels [4t,4t+4)
    const int p0 = g_ptr[v];
    const int deg = g_ptr[v + 1] - p0;

    __shared__ float sh_ws[4];
    __shared__ float sh_m[4];
    __shared__ int   sh_src[CAP];
    __shared__ float sh_w[CAP * 4];

    float dt[4];
    {
        float4 d4 = *reinterpret_cast<const float4*>(&g_dt[v * 4]);
        dt[0] = d4.x; dt[1] = d4.y; dt[2] = d4.z; dt[3] = d4.w;
    }

    if (deg <= CAP) {
        for (int e = t; e < deg; e += 64) {
            int sN = g_csr[p0 + e];
            sh_src[e] = sN;
            float4 s4 = *reinterpret_cast<const float4*>(&g_s[sN * 4]);
            sh_w[e * 4 + 0] = leaky02(s4.x + dt[0]);
            sh_w[e * 4 + 1] = leaky02(s4.y + dt[1]);
            sh_w[e * 4 + 2] = leaky02(s4.z + dt[2]);
            sh_w[e * 4 + 3] = leaky02(s4.w + dt[3]);
        }
        __syncthreads();
        // stats: warp w handles heads 2w and 2w+1
#pragma unroll
        for (int k = 0; k < 2; k++) {
            int hh = warp * 2 + k;
            float mx = -1e30f;
            for (int e = lane; e < deg; e += 32) mx = fmaxf(mx, sh_w[e * 4 + hh]);
#pragma unroll
            for (int o = 16; o > 0; o >>= 1) mx = fmaxf(mx, __shfl_xor_sync(0xffffffffu, mx, o));
            float sum = 0.f;
            for (int e = lane; e < deg; e += 32) {
                float w_ = __expf(sh_w[e * 4 + hh] - mx);
                sh_w[e * 4 + hh] = w_;
                sum += w_;
            }
#pragma unroll
            for (int o = 16; o > 0; o >>= 1) sum += __shfl_xor_sync(0xffffffffu, sum, o);
            if (lane == 0) sh_ws[hh] = sum;
        }
        __syncthreads();

        float4 acc = make_float4(0.f, 0.f, 0.f, 0.f);
        const float* __restrict__ hb = g_h + t * 4;
        int e = 0;
        for (; e + 3 < deg; e += 4) {
            float w0 = sh_w[(e+0)*4 + hd], w1 = sh_w[(e+1)*4 + hd];
            float w2 = sh_w[(e+2)*4 + hd], w3 = sh_w[(e+3)*4 + hd];
            float4 h0 = *reinterpret_cast<const float4*>(hb + (size_t)sh_src[e+0] * 256);
            float4 h1 = *reinterpret_cast<const float4*>(hb + (size_t)sh_src[e+1] * 256);
            float4 h2 = *reinterpret_cast<const float4*>(hb + (size_t)sh_src[e+2] * 256);
            float4 h3 = *reinterpret_cast<const float4*>(hb + (size_t)sh_src[e+3] * 256);
            acc.x += w0*h0.x + w1*h1.x + w2*h2.x + w3*h3.x;
            acc.y += w0*h0.y + w1*h1.y + w2*h2.y + w3*h3.y;
            acc.z += w0*h0.z + w1*h1.z + w2*h2.z + w3*h3.z;
            acc.w += w0*h0.w + w1*h1.w + w2*h2.w + w3*h3.w;
        }
        for (; e < deg; e++) {
            float w_ = sh_w[e*4 + hd];
            float4 h_ = *reinterpret_cast<const float4*>(hb + (size_t)sh_src[e] * 256);
            acc.x += w_*h_.x; acc.y += w_*h_.y; acc.z += w_*h_.z; acc.w += w_*h_.w;
        }
        float inv = 1.f / sh_ws[hd];
        float4 b4 = *reinterpret_cast<const float4*>(&bias[t * 4]);
        float4 o;
        o.x = fmaxf(acc.x * inv + b4.x, 0.f);
        o.y = fmaxf(acc.y * inv + b4.y, 0.f);
        o.z = fmaxf(acc.z * inv + b4.z, 0.f);
        o.w = fmaxf(acc.w * inv + b4.w, 0.f);
        *reinterpret_cast<float4*>(&outp[(size_t)v * 256 + t * 4]) = o;
        return;
    }

    // ---- fallback deg > CAP ----
#pragma unroll
    for (int k = 0; k < 2; k++) {
        int hh = warp * 2 + k;
        float mx = -1e30f;
        for (int e = lane; e < deg; e += 32) {
            int sN = g_csr[p0 + e];
            mx = fmaxf(mx, leaky02(g_s[sN * 4 + hh] + dt[hh]));
        }
#pragma unroll
        for (int o = 16; o > 0; o >>= 1) mx = fmaxf(mx, __shfl_xor_sync(0xffffffffu, mx, o));
        float sum = 0.f;
        for (int e = lane; e < deg; e += 32) {
            int sN = g_csr[p0 + e];
            sum += __expf(leaky02(g_s[sN * 4 + hh] + dt[hh]) - mx);
        }
#pragma unroll
        for (int o = 16; o > 0; o >>= 1) sum += __shfl_xor_sync(0xffffffffu, sum, o);
        if (lane == 0) { sh_m[hh] = mx; sh_ws[hh] = sum; }
    }
    __syncthreads();

    float4 acc = make_float4(0.f, 0.f, 0.f, 0.f);
    const float* __restrict__ hb = g_h + t * 4;
    for (int base = 0; base < deg; base += CAP) {
        int cnt = min(CAP, deg - base);
        for (int e = t; e < cnt; e += 64) {
            int sN = g_csr[p0 + base + e];
            sh_src[e] = sN;
            float4 s4 = *reinterpret_cast<const float4*>(&g_s[sN * 4]);
            sh_w[e*4+0] = __expf(leaky02(s4.x + dt[0]) - sh_m[0]);
            sh_w[e*4+1] = __expf(leaky02(s4.y + dt[1]) - sh_m[1]);
            sh_w[e*4+2] = __expf(leaky02(s4.z + dt[2]) - sh_m[2]);
            sh_w[e*4+3] = __expf(leaky02(s4.w + dt[3]) - sh_m[3]);
        }
        __syncthreads();
        for (int e = 0; e < cnt; e++) {
            float w_ = sh_w[e*4 + hd];
            float4 h_ = *reinterpret_cast<const float4*>(hb + (size_t)sh_src[e] * 256);
            acc.x += w_*h_.x; acc.y += w_*h_.y; acc.z += w_*h_.z; acc.w += w_*h_.w;
        }
        __syncthreads();
    }
    float inv = 1.f / sh_ws[hd];
    float4 b4 = *reinterpret_cast<const float4*>(&bias[t * 4]);
    float4 o;
    o.x = fmaxf(acc.x * inv + b4.x, 0.f);
    o.y = fmaxf(acc.y * inv + b4.y, 0.f);
    o.z = fmaxf(acc.z * inv + b4.z, 0.f);
    o.w = fmaxf(acc.w * inv + b4.w, 0.f);
    *reinterpret_cast<float4*>(&outp[(size_t)v * 256 + t * 4]) = o;
}

// ---------------- GAT aggregation H=1 (layer 3), 64 threads scalar ----------------
__global__ void gat_agg1_kernel(const float* __restrict__ bias) {
    float* __restrict__ outp = g_o3;
    const int v = blockIdx.x;
    const int t = threadIdx.x;      // 64
    const int lane = t & 31, warp = t >> 5;
    const int p0 = g_ptr[v];
    const int deg = g_ptr[v + 1] - p0;

    __shared__ float sh_ws[1];
    __shared__ float sh_m[1];
    __shared__ int   sh_src[CAP];
    __shared__ float sh_w[CAP];

    float dt0 = g_dt[v * 4];

    if (deg <= CAP) {
        for (int e = t; e < deg; e += 64) {
            int sN = g_csr[p0 + e];
            sh_src[e] = sN;
            sh_w[e] = leaky02(g_s[sN * 4] + dt0);
        }
        __syncthreads();
        if (warp == 0) {
            float mx = -1e30f;
            for (int e = lane; e < deg; e += 32) mx = fmaxf(mx, sh_w[e]);
#pragma unroll
            for (int o = 16; o > 0; o >>= 1) mx = fmaxf(mx, __shfl_xor_sync(0xffffffffu, mx, o));
            float sum = 0.f;
            for (int e = lane; e < deg; e += 32) {
                float w_ = __expf(sh_w[e] - mx);
                sh_w[e] = w_;
                sum += w_;
            }
#pragma unroll
            for (int o = 16; o > 0; o >>= 1) sum += __shfl_xor_sync(0xffffffffu, sum, o);
            if (lane == 0) sh_ws[0] = sum;
        }
        __syncthreads();

        float acc = 0.f;
        int e = 0;
        for (; e + 3 < deg; e += 4) {
            acc += sh_w[e+0] * g_h[(size_t)sh_src[e+0] * 64 + t];
            acc += sh_w[e+1] * g_h[(size_t)sh_src[e+1] * 64 + t];
            acc += sh_w[e+2] * g_h[(size_t)sh_src[e+2] * 64 + t];
            acc += sh_w[e+3] * g_h[(size_t)sh_src[e+3] * 64 + t];
        }
        for (; e < deg; e++) acc += sh_w[e] * g_h[(size_t)sh_src[e] * 64 + t];
        float o = acc / sh_ws[0] + bias[t];
        outp[(size_t)v * 64 + t] = fmaxf(o, 0.f);
        return;
    }

    // fallback
    if (warp == 0) {
        float mx = -1e30f;
        for (int e = lane; e < deg; e += 32) {
            int sN = g_csr[p0 + e];
            mx = fmaxf(mx, leaky02(g_s[sN * 4] + dt0));
        }
#pragma unroll
        for (int o = 16; o > 0; o >>= 1) mx = fmaxf(mx, __shfl_xor_sync(0xffffffffu, mx, o));
        float sum = 0.f;
        for (int e = lane; e < deg; e += 32) {
            int sN = g_csr[p0 + e];
            sum += __expf(leaky02(g_s[sN * 4] + dt0) - mx);
        }
#pragma unroll
        for (int o = 16; o > 0; o >>= 1) sum += __shfl_xor_sync(0xffffffffu, sum, o);
        if (lane == 0) { sh_m[0] = mx; sh_ws[0] = sum; }
    }
    __syncthreads();

    float acc = 0.f;
    for (int base = 0; base < deg; base += CAP) {
        int cnt = min(CAP, deg - base);
        for (int e = t; e < cnt; e += 64) {
            int sN = g_csr[p0 + base + e];
            sh_src[e] = sN;
            sh_w[e] = __expf(leaky02(g_s[sN * 4] + dt0) - sh_m[0]);
        }
        __syncthreads();
        for (int e = 0; e < cnt; e++)
            acc += sh_w[e] * g_h[(size_t)sh_src[e] * 64 + t];
        __syncthreads();
    }
    float o = acc / sh_ws[0] + bias[t];
    outp[(size_t)v * 64 + t] = fmaxf(o, 0.f);
}

// ---------------- fused pool + actor/critic heads ----------------
__global__ void heads_pool_kernel(const int* __restrict__ batch,
                                  const float* __restrict__ Wa1, const float* __restrict__ ba1,
                                  const float* __restrict__ Wa2, const float* __restrict__ ba2,
                                  const float* __restrict__ Wc1, const float* __restrict__ bc1,
                                  const float* __restrict__ Wc2, const float* __restrict__ bc2,
                                  float* __restrict__ out) {
    const int b = blockIdx.x;
    const int t = threadIdx.x;
    int lo = 0, hi = NN;
    while (lo < hi) { int mid = (lo + hi) >> 1; if (batch[mid] < b) lo = mid + 1; else hi = mid; }
    int start = lo;
    lo = start; hi = NN;
    while (lo < hi) { int mid = (lo + hi) >> 1; if (batch[mid] < b + 1) lo = mid + 1; else hi = mid; }
    int end = lo;
    int cnt = end - start;

    __shared__ float red[256];
    __shared__ float p[64], ha[64], hc[64];
    const int c = t & 63, stripe = t >> 6;
    float part = 0.f;
    for (int n = start + stripe; n < end; n += 4) part += g_o3[n * 64 + c];
    red[t] = part;
    __syncthreads();
    if (t < 64) {
        float s = red[t] + red[t + 64] + red[t + 128] + red[t + 192];
        float cc = cnt > 0 ? (float)cnt : 1.f;
        p[t] = s / cc;
    }
    __syncthreads();
    if (t < 64) {
        float aa = ba1[t], cv = bc1[t];
        for (int j = 0; j < 64; j++) { aa += p[j] * Wa1[j * 64 + t]; cv += p[j] * Wc1[j * 64 + t]; }
        ha[t] = fmaxf(aa, 0.f);
        hc[t] = fmaxf(cv, 0.f);
    }
    __syncthreads();
    for (int o = t; o < NEDGES_OUT; o += blockDim.x) {
        float acc = ba2[o];
        for (int j = 0; j < 64; j++) acc += ha[j] * Wa2[j * NEDGES_OUT + o];
        out[b * NEDGES_OUT + o] = tanhf(acc);
    }
    if (t == 0) {
        float acc = bc2[0];
        for (int j = 0; j < 64; j++) acc += hc[j] * Wc2[j];
        out[BGRAPH * NEDGES_OUT + b] = acc;
    }
}

// ---------------- launch ----------------
extern "C" void kernel_launch(void* const* d_in, const int* in_sizes, int n_in,
                              void* d_out, int out_size) {
    const float* x     = (const float*)d_in[0];
    const int*   ei    = (const int*)d_in[1];
    const int*   batch = (const int*)d_in[2];
    const float* W1  = (const float*)d_in[3];
    const float* as1 = (const float*)d_in[4];
    const float* ad1 = (const float*)d_in[5];
    const float* b1  = (const float*)d_in[6];
    const float* W2  = (const float*)d_in[7];
    const float* as2 = (const float*)d_in[8];
    const float* ad2 = (const float*)d_in[9];
    const float* b2  = (const float*)d_in[10];
    const float* W3  = (const float*)d_in[11];
    const float* as3 = (const float*)d_in[12];
    const float* ad3 = (const float*)d_in[13];
    const float* b3  = (const float*)d_in[14];
    const float* Wa1 = (const float*)d_in[15];
    const float* ba1 = (const float*)d_in[16];
    const float* Wa2 = (const float*)d_in[17];
    const float* ba2 = (const float*)d_in[18];
    const float* Wc1 = (const float*)d_in[19];
    const float* bc1 = (const float*)d_in[20];
    const float* Wc2 = (const float*)d_in[21];
    const float* bc2 = (const float*)d_in[22];
    float* out = (float*)d_out;

    zero_deg_kernel<<<(NN + 256) / 256, 256>>>();
    count_deg_kernel<<<(EALL + 255) / 256, 256>>>(ei);
    scan_kernel<<<1, 1024>>>();
    scatter_kernel<<<(EALL + 255) / 256, 256>>>(ei);

    const int MB = (NN + 127) / 128;

    sgemm_fused_kernel<128, 4><<<dim3(2, MB), 256>>>(x, 0, W1, as1, ad1, NN, 128);
    gat_agg4_kernel<<<NN, 64>>>(b1, 1);

    sgemm_fused_kernel<128, 4><<<dim3(2, MB), 256>>>(x, 1, W2, as2, ad2, NN, 256);
    gat_agg4_kernel<<<NN, 64>>>(b2, 2);

    sgemm_fused_kernel<64, 1><<<dim3(1, MB), 256>>>(x, 2, W3, as3, ad3, NN, 256);
    gat_agg1_kernel<<<NN, 64>>>(b3);

    heads_pool_kernel<<<BGRAPH, 256>>>(batch, Wa1, ba1, Wa2, ba2, Wc1, bc1, Wc2, bc2, out);
}